// round 13
// baseline (speedup 1.0000x reference)
#include <cuda_runtime.h>
#include <cuda_bf16.h>
#include <cstdint>

// ---------------- static problem bounds ----------------
#define MAXN 100000
#define MAXE 1600000
#define HD   128

// ---------------- device scratch (no allocations allowed) ----------------
__device__ float g_feat[(size_t)MAXN * HD];
__device__ float g_res [(size_t)MAXN * HD];
__device__ float g_hA  [(size_t)MAXN * HD];
__device__ float g_hB  [(size_t)MAXN * HD];
__device__ float g_el  [MAXN * 4];
__device__ float g_er  [MAXN * 4];
__device__ int   g_deg [MAXN];
__device__ int   g_tmp [MAXN];
__device__ int   g_bsum[1024];
__device__ int   g_rowptr[MAXN + 1];
__device__ int   g_wpos[MAXN];
__device__ int   g_srcs[MAXE];
__device__ float g_ews [MAXE];

// ---------------- f32x2 packed-FMA helpers (sm_103a) ----------------
__device__ __forceinline__ unsigned long long pack2(float x, float y) {
    unsigned long long r;
    asm("mov.b64 %0, {%1, %2};" : "=l"(r) : "f"(x), "f"(y));
    return r;
}
__device__ __forceinline__ void unpack2(unsigned long long v, float& x, float& y) {
    asm("mov.b64 {%0, %1}, %2;" : "=f"(x), "=f"(y) : "l"(v));
}
__device__ __forceinline__ void ffma2(unsigned long long& d,
                                      unsigned long long a,
                                      unsigned long long b) {
    asm("fma.rn.f32x2 %0, %1, %2, %0;" : "+l"(d) : "l"(a), "l"(b));
}

// ---------------- CSR build ----------------
__global__ void k_hist(const int* __restrict__ dst, int* __restrict__ deg, int E) {
    int i = blockIdx.x * blockDim.x + threadIdx.x;
    if (i < E) atomicAdd(&deg[dst[i]], 1);
}

#define SCAN_T 1024
__global__ void k_scan1(const int* __restrict__ deg, int* __restrict__ tmp,
                        int* __restrict__ bsum, int N) {
    __shared__ int sh[SCAN_T];
    int i = blockIdx.x * SCAN_T + threadIdx.x;
    int v = (i < N) ? deg[i] : 0;
    sh[threadIdx.x] = v;
    __syncthreads();
    for (int off = 1; off < SCAN_T; off <<= 1) {
        int t = (threadIdx.x >= off) ? sh[threadIdx.x - off] : 0;
        __syncthreads();
        sh[threadIdx.x] += t;
        __syncthreads();
    }
    if (i < N) tmp[i] = sh[threadIdx.x];
    if (threadIdx.x == SCAN_T - 1) bsum[blockIdx.x] = sh[SCAN_T - 1];
}

__global__ void k_scan2(int* __restrict__ bsum, int nb) {
    __shared__ int sh[SCAN_T];
    int v = (threadIdx.x < nb) ? bsum[threadIdx.x] : 0;
    sh[threadIdx.x] = v;
    __syncthreads();
    for (int off = 1; off < SCAN_T; off <<= 1) {
        int t = (threadIdx.x >= off) ? sh[threadIdx.x - off] : 0;
        __syncthreads();
        sh[threadIdx.x] += t;
        __syncthreads();
    }
    if (threadIdx.x < nb) bsum[threadIdx.x] = sh[threadIdx.x];
}

__global__ void k_scan3(const int* __restrict__ deg, const int* __restrict__ tmp,
                        const int* __restrict__ bsum, int* __restrict__ rowptr,
                        int* __restrict__ wpos, int N) {
    int i = blockIdx.x * blockDim.x + threadIdx.x;
    if (i >= N) return;
    int b = i >> 10;
    int boff = (b > 0) ? bsum[b - 1] : 0;
    int incl = tmp[i] + boff;
    rowptr[i + 1] = incl;
    wpos[i] = incl - deg[i];
    if (i == 0) rowptr[0] = 0;
}

__global__ void k_scatter(const int* __restrict__ src, const int* __restrict__ dst,
                          const float* __restrict__ ew, int* __restrict__ wpos,
                          int* __restrict__ srcs, float* __restrict__ ews, int E) {
    int i = blockIdx.x * blockDim.x + threadIdx.x;
    if (i >= E) return;
    int d = dst[i];
    int p = atomicAdd(&wpos[d], 1);
    srcs[p] = src[i];
    ews[p]  = ew[i];
}

// ---------------- SGEMM: C[N x 128] = A[N x K] @ B[K x 128] (fp32, FFMA2) --------
__global__ __launch_bounds__(256, 2)
void k_gemm(const float* __restrict__ A, const float* __restrict__ B,
            float* __restrict__ C, int N, int K) {
    __shared__ float As[16][132];   // [k][m], padded
    __shared__ float Bs[16][128];   // [k][n]
    const int tid = threadIdx.x;
    const int tx = tid & 15;        // -> output cols tx*4..+3 and 64+tx*4..+3
    const int ty = tid >> 4;        // -> output rows ty*8..+7
    const int row0 = blockIdx.x * 128;

    unsigned long long acc[8][4];
#pragma unroll
    for (int i = 0; i < 8; i++)
#pragma unroll
        for (int j = 0; j < 4; j++) acc[i][j] = 0ULL;

    for (int kt = 0; kt < K; kt += 16) {
#pragma unroll
        for (int it = 0; it < 2; ++it) {
            int id = tid + it * 256;          // 0..511
            int m  = id >> 2;                 // 0..127
            int kq = (id & 3) << 2;           // 0,4,8,12
            int grow = row0 + m;
            float4 v = make_float4(0.f, 0.f, 0.f, 0.f);
            if (grow < N)
                v = *reinterpret_cast<const float4*>(A + (size_t)grow * K + kt + kq);
            As[kq + 0][m] = v.x; As[kq + 1][m] = v.y;
            As[kq + 2][m] = v.z; As[kq + 3][m] = v.w;
        }
#pragma unroll
        for (int it = 0; it < 2; ++it) {
            int id = tid + it * 256;
            int kr = id >> 5;                 // 0..15
            int c  = (id & 31) << 2;          // 0..124
            *reinterpret_cast<float4*>(&Bs[kr][c]) =
                *reinterpret_cast<const float4*>(B + (size_t)(kt + kr) * 128 + c);
        }
        __syncthreads();
#pragma unroll
        for (int k = 0; k < 16; k++) {
            float4 a0 = *reinterpret_cast<const float4*>(&As[k][ty * 8]);
            float4 a1 = *reinterpret_cast<const float4*>(&As[k][ty * 8 + 4]);
            float4 b0 = *reinterpret_cast<const float4*>(&Bs[k][tx * 4]);
            float4 b1 = *reinterpret_cast<const float4*>(&Bs[k][64 + tx * 4]);
            unsigned long long bp[4] = { pack2(b0.x, b0.y), pack2(b0.z, b0.w),
                                         pack2(b1.x, b1.y), pack2(b1.z, b1.w) };
            float av[8] = { a0.x, a0.y, a0.z, a0.w, a1.x, a1.y, a1.z, a1.w };
#pragma unroll
            for (int i = 0; i < 8; i++) {
                unsigned long long ap = pack2(av[i], av[i]);
#pragma unroll
                for (int j = 0; j < 4; j++) ffma2(acc[i][j], ap, bp[j]);
            }
        }
        __syncthreads();
    }
#pragma unroll
    for (int i = 0; i < 8; i++) {
        int r = row0 + ty * 8 + i;
        if (r < N) {
            float x0, x1, x2, x3;
            unpack2(acc[i][0], x0, x1); unpack2(acc[i][1], x2, x3);
            *reinterpret_cast<float4*>(C + (size_t)r * 128 + tx * 4) =
                make_float4(x0, x1, x2, x3);
            unpack2(acc[i][2], x0, x1); unpack2(acc[i][3], x2, x3);
            *reinterpret_cast<float4*>(C + (size_t)r * 128 + 64 + tx * 4) =
                make_float4(x0, x1, x2, x3);
        }
    }
}

// ---------------- el/er = einsum(feat, al/ar) per node/head ----------------
__global__ __launch_bounds__(128)
void k_elr(const float* __restrict__ feat, const float* __restrict__ al,
           const float* __restrict__ ar, float* __restrict__ el,
           float* __restrict__ er, int N) {
    int n = blockIdx.x;
    int tid = threadIdx.x, w = tid >> 5, lane = tid & 31;
    float v = feat[(size_t)n * 128 + tid];
    float pl = v * al[tid];
    float pr = v * ar[tid];
#pragma unroll
    for (int off = 16; off > 0; off >>= 1) {
        pl += __shfl_xor_sync(0xffffffffu, pl, off);
        pr += __shfl_xor_sync(0xffffffffu, pr, off);
    }
    if (lane == 0) { el[n * 4 + w] = pl; er[n * 4 + w] = pr; }
}

// ---- fused: segment-softmax attention + aggregate + residual + bias + ELU + LN --
__global__ __launch_bounds__(128)
void k_edge(const float* __restrict__ feat, const float* __restrict__ el,
            const float* __restrict__ er, const int* __restrict__ rowptr,
            const int* __restrict__ srcs, const float* __restrict__ ews,
            const float* __restrict__ res, const float* __restrict__ bias,
            const float* __restrict__ lng, const float* __restrict__ lnb,
            float* __restrict__ out, int N, int act) {
    int n = blockIdx.x;
    int tid = threadIdx.x;
    int w = tid >> 5, lane = tid & 31;
    int base = rowptr[n];
    int deg  = rowptr[n + 1] - base;
    float er_w = er[n * 4 + w];

    // phase 1: online softmax (max m, denominator s) per head (= per warp)
    float m = -1e30f, s = 0.f;
    for (int j = lane; j < deg; j += 32) {
        int sj = __ldg(srcs + base + j);
        float e = __ldg(el + sj * 4 + w) + er_w;
        e = e > 0.f ? e : 0.2f * e;
        float mn = fmaxf(m, e);
        s = s * __expf(m - mn) + __expf(e - mn);
        m = mn;
    }
#pragma unroll
    for (int off = 16; off > 0; off >>= 1) {
        float mo = __shfl_xor_sync(0xffffffffu, m, off);
        float so = __shfl_xor_sync(0xffffffffu, s, off);
        float mn = fmaxf(m, mo);
        s = s * __expf(m - mn) + so * __expf(mo - mn);
        m = mn;
    }
    float inv = (s > 0.f) ? 1.f / s : 0.f;

    // phase 2: weighted aggregation. Lane owns output dim d=lane of head w.
    float acc = 0.f;
    const float* fp = feat + w * 32 + lane;
    for (int j0 = 0; j0 < deg; j0 += 32) {
        int jme = j0 + lane;
        int sj_l = 0; float a_l = 0.f;
        if (jme < deg) {
            sj_l = __ldg(srcs + base + jme);
            float e = __ldg(el + sj_l * 4 + w) + er_w;
            e = e > 0.f ? e : 0.2f * e;
            a_l = __expf(e - m) * inv * __ldg(ews + base + jme);
        }
        int cnt = min(32, deg - j0);
        for (int jj = 0; jj < cnt; ++jj) {
            int   sj = __shfl_sync(0xffffffffu, sj_l, jj);
            float a  = __shfl_sync(0xffffffffu, a_l, jj);
            acc = fmaf(a, __ldg(fp + (size_t)sj * 128), acc);
        }
    }

    // residual + bias + activation
    float v = acc + res[(size_t)n * 128 + tid] + bias[tid];
    if (act) v = (v > 0.f) ? v : expm1f(v);

    // layernorm over the 128 features of this node (1 value per thread)
    float sm = v, sq = v * v;
#pragma unroll
    for (int off = 16; off > 0; off >>= 1) {
        sm += __shfl_xor_sync(0xffffffffu, sm, off);
        sq += __shfl_xor_sync(0xffffffffu, sq, off);
    }
    __shared__ float rs[4], rq[4];
    if (lane == 0) { rs[w] = sm; rq[w] = sq; }
    __syncthreads();
    sm = rs[0] + rs[1] + rs[2] + rs[3];
    sq = rq[0] + rq[1] + rq[2] + rq[3];
    float mu   = sm * (1.f / 128.f);
    float var  = sq * (1.f / 128.f) - mu * mu;
    float rstd = rsqrtf(var + 1e-5f);
    out[(size_t)n * 128 + tid] = (v - mu) * rstd * lng[tid] + lnb[tid];
}

// ---------------- launch ----------------
extern "C" void kernel_launch(void* const* d_in, const int* in_sizes, int n_in,
                              void* d_out, int out_size) {
    const float* x    = (const float*)d_in[0];
    const int*   src  = (const int*)  d_in[1];
    const int*   dst  = (const int*)  d_in[2];
    const float* ew   = (const float*)d_in[3];
    const float* W0   = (const float*)d_in[4];
    const float* al0  = (const float*)d_in[5];
    const float* ar0  = (const float*)d_in[6];
    const float* b0   = (const float*)d_in[7];
    const float* rW0  = (const float*)d_in[8];
    const float* g0   = (const float*)d_in[9];
    const float* be0  = (const float*)d_in[10];
    const float* W1   = (const float*)d_in[11];
    const float* al1  = (const float*)d_in[12];
    const float* ar1  = (const float*)d_in[13];
    const float* b1   = (const float*)d_in[14];
    const float* g1   = (const float*)d_in[15];
    const float* be1  = (const float*)d_in[16];
    const float* W2   = (const float*)d_in[17];
    const float* al2  = (const float*)d_in[18];
    const float* ar2  = (const float*)d_in[19];
    const float* b2   = (const float*)d_in[20];
    const float* g2   = (const float*)d_in[21];
    const float* be2  = (const float*)d_in[22];

    int E   = in_sizes[1];
    int Fin = in_sizes[4] / 128;          // W0 is [F_in, 128]
    int N   = in_sizes[0] / Fin;

    float *p_feat, *p_res, *p_hA, *p_hB, *p_el, *p_er, *p_ews;
    int *p_deg, *p_tmp, *p_bsum, *p_rowptr, *p_wpos, *p_srcs;
    cudaGetSymbolAddress((void**)&p_feat,   g_feat);
    cudaGetSymbolAddress((void**)&p_res,    g_res);
    cudaGetSymbolAddress((void**)&p_hA,     g_hA);
    cudaGetSymbolAddress((void**)&p_hB,     g_hB);
    cudaGetSymbolAddress((void**)&p_el,     g_el);
    cudaGetSymbolAddress((void**)&p_er,     g_er);
    cudaGetSymbolAddress((void**)&p_ews,    g_ews);
    cudaGetSymbolAddress((void**)&p_deg,    g_deg);
    cudaGetSymbolAddress((void**)&p_tmp,    g_tmp);
    cudaGetSymbolAddress((void**)&p_bsum,   g_bsum);
    cudaGetSymbolAddress((void**)&p_rowptr, g_rowptr);
    cudaGetSymbolAddress((void**)&p_wpos,   g_wpos);
    cudaGetSymbolAddress((void**)&p_srcs,   g_srcs);

    // ---- build dst-CSR (reused by all 3 layers) ----
    cudaMemsetAsync(p_deg, 0, (size_t)N * sizeof(int));
    int eb = (E + 255) / 256;
    k_hist<<<eb, 256>>>(dst, p_deg, E);
    int nb = (N + SCAN_T - 1) / SCAN_T;
    k_scan1<<<nb, SCAN_T>>>(p_deg, p_tmp, p_bsum, N);
    k_scan2<<<1, SCAN_T>>>(p_bsum, nb);
    k_scan3<<<(N + 255) / 256, 256>>>(p_deg, p_tmp, p_bsum, p_rowptr, p_wpos, N);
    k_scatter<<<eb, 256>>>(src, dst, ew, p_wpos, p_srcs, p_ews, E);

    int gb = (N + 127) / 128;

    // ---- layer 0 (in=x, K=Fin, residual = x @ resW0, ELU) ----
    k_gemm<<<gb, 256>>>(x, W0,  p_feat, N, Fin);
    k_gemm<<<gb, 256>>>(x, rW0, p_res,  N, Fin);
    k_elr <<<N, 128>>>(p_feat, al0, ar0, p_el, p_er, N);
    k_edge<<<N, 128>>>(p_feat, p_el, p_er, p_rowptr, p_srcs, p_ews,
                       p_res, b0, g0, be0, p_hA, N, 1);

    // ---- layer 1 (identity residual, ELU) ----
    k_gemm<<<gb, 256>>>(p_hA, W1, p_feat, N, 128);
    k_elr <<<N, 128>>>(p_feat, al1, ar1, p_el, p_er, N);
    k_edge<<<N, 128>>>(p_feat, p_el, p_er, p_rowptr, p_srcs, p_ews,
                       p_hA, b1, g1, be1, p_hB, N, 1);

    // ---- layer 2 (identity residual, no activation) ----
    k_gemm<<<gb, 256>>>(p_hB, W2, p_feat, N, 128);
    k_elr <<<N, 128>>>(p_feat, al2, ar2, p_el, p_er, N);
    k_edge<<<N, 128>>>(p_feat, p_el, p_er, p_rowptr, p_srcs, p_ews,
                       p_hB, b2, g2, be2, (float*)d_out, N, 0);
}

// round 14
// speedup vs baseline: 1.0032x; 1.0032x over previous
#include <cuda_runtime.h>
#include <cuda_bf16.h>
#include <cstdint>

// ---------------- static problem bounds ----------------
#define MAXN 100000
#define MAXE 1600000
#define HD   128

// ---------------- device scratch (no allocations allowed) ----------------
__device__ float g_feat[(size_t)MAXN * HD];
__device__ float g_res [(size_t)MAXN * HD];
__device__ float g_hA  [(size_t)MAXN * HD];
__device__ float g_hB  [(size_t)MAXN * HD];
__device__ float g_el  [MAXN * 4];
__device__ float g_er  [MAXN * 4];
__device__ int   g_deg [MAXN];
__device__ int   g_tmp [MAXN];
__device__ int   g_bsum[1024];
__device__ int   g_rowptr[MAXN + 1];
__device__ int   g_wpos[MAXN];
__device__ int   g_srcs[MAXE];
__device__ float g_ews [MAXE];

// ---------------- f32x2 packed-FMA helpers (sm_103a) ----------------
__device__ __forceinline__ unsigned long long pack2(float x, float y) {
    unsigned long long r;
    asm("mov.b64 %0, {%1, %2};" : "=l"(r) : "f"(x), "f"(y));
    return r;
}
__device__ __forceinline__ void unpack2(unsigned long long v, float& x, float& y) {
    asm("mov.b64 {%0, %1}, %2;" : "=f"(x), "=f"(y) : "l"(v));
}
__device__ __forceinline__ void ffma2(unsigned long long& d,
                                      unsigned long long a,
                                      unsigned long long b) {
    asm("fma.rn.f32x2 %0, %1, %2, %0;" : "+l"(d) : "l"(a), "l"(b));
}

// ---------------- CSR build ----------------
__global__ void k_hist(const int* __restrict__ dst, int* __restrict__ deg, int E) {
    int i = blockIdx.x * blockDim.x + threadIdx.x;
    if (i < E) atomicAdd(&deg[dst[i]], 1);
}

#define SCAN_T 1024
__global__ void k_scan1(const int* __restrict__ deg, int* __restrict__ tmp,
                        int* __restrict__ bsum, int N) {
    __shared__ int sh[SCAN_T];
    int i = blockIdx.x * SCAN_T + threadIdx.x;
    int v = (i < N) ? deg[i] : 0;
    sh[threadIdx.x] = v;
    __syncthreads();
    for (int off = 1; off < SCAN_T; off <<= 1) {
        int t = (threadIdx.x >= off) ? sh[threadIdx.x - off] : 0;
        __syncthreads();
        sh[threadIdx.x] += t;
        __syncthreads();
    }
    if (i < N) tmp[i] = sh[threadIdx.x];
    if (threadIdx.x == SCAN_T - 1) bsum[blockIdx.x] = sh[SCAN_T - 1];
}

__global__ void k_scan2(int* __restrict__ bsum, int nb) {
    __shared__ int sh[SCAN_T];
    int v = (threadIdx.x < nb) ? bsum[threadIdx.x] : 0;
    sh[threadIdx.x] = v;
    __syncthreads();
    for (int off = 1; off < SCAN_T; off <<= 1) {
        int t = (threadIdx.x >= off) ? sh[threadIdx.x - off] : 0;
        __syncthreads();
        sh[threadIdx.x] += t;
        __syncthreads();
    }
    if (threadIdx.x < nb) bsum[threadIdx.x] = sh[threadIdx.x];
}

__global__ void k_scan3(const int* __restrict__ deg, const int* __restrict__ tmp,
                        const int* __restrict__ bsum, int* __restrict__ rowptr,
                        int* __restrict__ wpos, int N) {
    int i = blockIdx.x * blockDim.x + threadIdx.x;
    if (i >= N) return;
    int b = i >> 10;
    int boff = (b > 0) ? bsum[b - 1] : 0;
    int incl = tmp[i] + boff;
    rowptr[i + 1] = incl;
    wpos[i] = incl - deg[i];
    if (i == 0) rowptr[0] = 0;
}

__global__ void k_scatter(const int* __restrict__ src, const int* __restrict__ dst,
                          const float* __restrict__ ew, int* __restrict__ wpos,
                          int* __restrict__ srcs, float* __restrict__ ews, int E) {
    int i = blockIdx.x * blockDim.x + threadIdx.x;
    if (i >= E) return;
    int d = dst[i];
    int p = atomicAdd(&wpos[d], 1);
    srcs[p] = src[i];
    ews[p]  = ew[i];
}

// ---------------- SGEMM: C[N x 128] = A[N x K] @ B[K x 128] (fp32, FFMA2) --------
__global__ __launch_bounds__(256, 2)
void k_gemm(const float* __restrict__ A, const float* __restrict__ B,
            float* __restrict__ C, int N, int K) {
    __shared__ float As[16][132];   // [k][m], padded
    __shared__ float Bs[16][128];   // [k][n]
    const int tid = threadIdx.x;
    const int tx = tid & 15;        // -> output cols tx*4..+3 and 64+tx*4..+3
    const int ty = tid >> 4;        // -> output rows ty*8..+7
    const int row0 = blockIdx.x * 128;

    unsigned long long acc[8][4];
#pragma unroll
    for (int i = 0; i < 8; i++)
#pragma unroll
        for (int j = 0; j < 4; j++) acc[i][j] = 0ULL;

    for (int kt = 0; kt < K; kt += 16) {
#pragma unroll
        for (int it = 0; it < 2; ++it) {
            int id = tid + it * 256;          // 0..511
            int m  = id >> 2;                 // 0..127
            int kq = (id & 3) << 2;           // 0,4,8,12
            int grow = row0 + m;
            float4 v = make_float4(0.f, 0.f, 0.f, 0.f);
            if (grow < N)
                v = *reinterpret_cast<const float4*>(A + (size_t)grow * K + kt + kq);
            As[kq + 0][m] = v.x; As[kq + 1][m] = v.y;
            As[kq + 2][m] = v.z; As[kq + 3][m] = v.w;
        }
#pragma unroll
        for (int it = 0; it < 2; ++it) {
            int id = tid + it * 256;
            int kr = id >> 5;                 // 0..15
            int c  = (id & 31) << 2;          // 0..124
            *reinterpret_cast<float4*>(&Bs[kr][c]) =
                *reinterpret_cast<const float4*>(B + (size_t)(kt + kr) * 128 + c);
        }
        __syncthreads();
#pragma unroll
        for (int k = 0; k < 16; k++) {
            float4 a0 = *reinterpret_cast<const float4*>(&As[k][ty * 8]);
            float4 a1 = *reinterpret_cast<const float4*>(&As[k][ty * 8 + 4]);
            float4 b0 = *reinterpret_cast<const float4*>(&Bs[k][tx * 4]);
            float4 b1 = *reinterpret_cast<const float4*>(&Bs[k][64 + tx * 4]);
            unsigned long long bp[4] = { pack2(b0.x, b0.y), pack2(b0.z, b0.w),
                                         pack2(b1.x, b1.y), pack2(b1.z, b1.w) };
            float av[8] = { a0.x, a0.y, a0.z, a0.w, a1.x, a1.y, a1.z, a1.w };
#pragma unroll
            for (int i = 0; i < 8; i++) {
                unsigned long long ap = pack2(av[i], av[i]);
#pragma unroll
                for (int j = 0; j < 4; j++) ffma2(acc[i][j], ap, bp[j]);
            }
        }
        __syncthreads();
    }
#pragma unroll
    for (int i = 0; i < 8; i++) {
        int r = row0 + ty * 8 + i;
        if (r < N) {
            float x0, x1, x2, x3;
            unpack2(acc[i][0], x0, x1); unpack2(acc[i][1], x2, x3);
            *reinterpret_cast<float4*>(C + (size_t)r * 128 + tx * 4) =
                make_float4(x0, x1, x2, x3);
            unpack2(acc[i][2], x0, x1); unpack2(acc[i][3], x2, x3);
            *reinterpret_cast<float4*>(C + (size_t)r * 128 + 64 + tx * 4) =
                make_float4(x0, x1, x2, x3);
        }
    }
}

// ---------------- el/er = einsum(feat, al/ar) per node/head ----------------
__global__ __launch_bounds__(128)
void k_elr(const float* __restrict__ feat, const float* __restrict__ al,
           const float* __restrict__ ar, float* __restrict__ el,
           float* __restrict__ er, int N) {
    int n = blockIdx.x;
    int tid = threadIdx.x, w = tid >> 5, lane = tid & 31;
    float v = feat[(size_t)n * 128 + tid];
    float pl = v * al[tid];
    float pr = v * ar[tid];
#pragma unroll
    for (int off = 16; off > 0; off >>= 1) {
        pl += __shfl_xor_sync(0xffffffffu, pl, off);
        pr += __shfl_xor_sync(0xffffffffu, pr, off);
    }
    if (lane == 0) { el[n * 4 + w] = pl; er[n * 4 + w] = pr; }
}

// ---- fused: segment-softmax attention + aggregate + residual + bias + ELU + LN --
__global__ __launch_bounds__(128)
void k_edge(const float* __restrict__ feat, const float* __restrict__ el,
            const float* __restrict__ er, const int* __restrict__ rowptr,
            const int* __restrict__ srcs, const float* __restrict__ ews,
            const float* __restrict__ res, const float* __restrict__ bias,
            const float* __restrict__ lng, const float* __restrict__ lnb,
            float* __restrict__ out, int N, int act) {
    int n = blockIdx.x;
    int tid = threadIdx.x;
    int w = tid >> 5, lane = tid & 31;
    int base = rowptr[n];
    int deg  = rowptr[n + 1] - base;
    float er_w = er[n * 4 + w];

    // phase 1: online softmax (max m, denominator s) per head (= per warp)
    float m = -1e30f, s = 0.f;
    for (int j = lane; j < deg; j += 32) {
        int sj = __ldg(srcs + base + j);
        float e = __ldg(el + sj * 4 + w) + er_w;
        e = e > 0.f ? e : 0.2f * e;
        float mn = fmaxf(m, e);
        s = s * __expf(m - mn) + __expf(e - mn);
        m = mn;
    }
#pragma unroll
    for (int off = 16; off > 0; off >>= 1) {
        float mo = __shfl_xor_sync(0xffffffffu, m, off);
        float so = __shfl_xor_sync(0xffffffffu, s, off);
        float mn = fmaxf(m, mo);
        s = s * __expf(m - mn) + so * __expf(mo - mn);
        m = mn;
    }
    float inv = (s > 0.f) ? 1.f / s : 0.f;

    // phase 2: weighted aggregation. Lane owns output dim d=lane of head w.
    float acc = 0.f;
    const float* fp = feat + w * 32 + lane;
    for (int j0 = 0; j0 < deg; j0 += 32) {
        int jme = j0 + lane;
        int sj_l = 0; float a_l = 0.f;
        if (jme < deg) {
            sj_l = __ldg(srcs + base + jme);
            float e = __ldg(el + sj_l * 4 + w) + er_w;
            e = e > 0.f ? e : 0.2f * e;
            a_l = __expf(e - m) * inv * __ldg(ews + base + jme);
        }
        int cnt = min(32, deg - j0);
        for (int jj = 0; jj < cnt; ++jj) {
            int   sj = __shfl_sync(0xffffffffu, sj_l, jj);
            float a  = __shfl_sync(0xffffffffu, a_l, jj);
            acc = fmaf(a, __ldg(fp + (size_t)sj * 128), acc);
        }
    }

    // residual + bias + activation
    float v = acc + res[(size_t)n * 128 + tid] + bias[tid];
    if (act) v = (v > 0.f) ? v : expm1f(v);

    // layernorm over the 128 features of this node (1 value per thread)
    float sm = v, sq = v * v;
#pragma unroll
    for (int off = 16; off > 0; off >>= 1) {
        sm += __shfl_xor_sync(0xffffffffu, sm, off);
        sq += __shfl_xor_sync(0xffffffffu, sq, off);
    }
    __shared__ float rs[4], rq[4];
    if (lane == 0) { rs[w] = sm; rq[w] = sq; }
    __syncthreads();
    sm = rs[0] + rs[1] + rs[2] + rs[3];
    sq = rq[0] + rq[1] + rq[2] + rq[3];
    float mu   = sm * (1.f / 128.f);
    float var  = sq * (1.f / 128.f) - mu * mu;
    float rstd = rsqrtf(var + 1e-5f);
    out[(size_t)n * 128 + tid] = (v - mu) * rstd * lng[tid] + lnb[tid];
}

// ---------------- launch ----------------
extern "C" void kernel_launch(void* const* d_in, const int* in_sizes, int n_in,
                              void* d_out, int out_size) {
    const float* x    = (const float*)d_in[0];
    const int*   src  = (const int*)  d_in[1];
    const int*   dst  = (const int*)  d_in[2];
    const float* ew   = (const float*)d_in[3];
    const float* W0   = (const float*)d_in[4];
    const float* al0  = (const float*)d_in[5];
    const float* ar0  = (const float*)d_in[6];
    const float* b0   = (const float*)d_in[7];
    const float* rW0  = (const float*)d_in[8];
    const float* g0   = (const float*)d_in[9];
    const float* be0  = (const float*)d_in[10];
    const float* W1   = (const float*)d_in[11];
    const float* al1  = (const float*)d_in[12];
    const float* ar1  = (const float*)d_in[13];
    const float* b1   = (const float*)d_in[14];
    const float* g1   = (const float*)d_in[15];
    const float* be1  = (const float*)d_in[16];
    const float* W2   = (const float*)d_in[17];
    const float* al2  = (const float*)d_in[18];
    const float* ar2  = (const float*)d_in[19];
    const float* b2   = (const float*)d_in[20];
    const float* g2   = (const float*)d_in[21];
    const float* be2  = (const float*)d_in[22];

    int E   = in_sizes[1];
    int Fin = in_sizes[4] / 128;          // W0 is [F_in, 128]
    int N   = in_sizes[0] / Fin;

    float *p_feat, *p_res, *p_hA, *p_hB, *p_el, *p_er, *p_ews;
    int *p_deg, *p_tmp, *p_bsum, *p_rowptr, *p_wpos, *p_srcs;
    cudaGetSymbolAddress((void**)&p_feat,   g_feat);
    cudaGetSymbolAddress((void**)&p_res,    g_res);
    cudaGetSymbolAddress((void**)&p_hA,     g_hA);
    cudaGetSymbolAddress((void**)&p_hB,     g_hB);
    cudaGetSymbolAddress((void**)&p_el,     g_el);
    cudaGetSymbolAddress((void**)&p_er,     g_er);
    cudaGetSymbolAddress((void**)&p_ews,    g_ews);
    cudaGetSymbolAddress((void**)&p_deg,    g_deg);
    cudaGetSymbolAddress((void**)&p_tmp,    g_tmp);
    cudaGetSymbolAddress((void**)&p_bsum,   g_bsum);
    cudaGetSymbolAddress((void**)&p_rowptr, g_rowptr);
    cudaGetSymbolAddress((void**)&p_wpos,   g_wpos);
    cudaGetSymbolAddress((void**)&p_srcs,   g_srcs);

    // ---- build dst-CSR (reused by all 3 layers) ----
    cudaMemsetAsync(p_deg, 0, (size_t)N * sizeof(int));
    int eb = (E + 255) / 256;
    k_hist<<<eb, 256>>>(dst, p_deg, E);
    int nb = (N + SCAN_T - 1) / SCAN_T;
    k_scan1<<<nb, SCAN_T>>>(p_deg, p_tmp, p_bsum, N);
    k_scan2<<<1, SCAN_T>>>(p_bsum, nb);
    k_scan3<<<(N + 255) / 256, 256>>>(p_deg, p_tmp, p_bsum, p_rowptr, p_wpos, N);
    k_scatter<<<eb, 256>>>(src, dst, ew, p_wpos, p_srcs, p_ews, E);

    int gb = (N + 127) / 128;

    // ---- layer 0 (in=x, K=Fin, residual = x @ resW0, ELU) ----
    k_gemm<<<gb, 256>>>(x, W0,  p_feat, N, Fin);
    k_gemm<<<gb, 256>>>(x, rW0, p_res,  N, Fin);
    k_elr <<<N, 128>>>(p_feat, al0, ar0, p_el, p_er, N);
    k_edge<<<N, 128>>>(p_feat, p_el, p_er, p_rowptr, p_srcs, p_ews,
                       p_res, b0, g0, be0, p_hA, N, 1);

    // ---- layer 1 (identity residual, ELU) ----
    k_gemm<<<gb, 256>>>(p_hA, W1, p_feat, N, 128);
    k_elr <<<N, 128>>>(p_feat, al1, ar1, p_el, p_er, N);
    k_edge<<<N, 128>>>(p_feat, p_el, p_er, p_rowptr, p_srcs, p_ews,
                       p_hA, b1, g1, be1, p_hB, N, 1);

    // ---- layer 2 (identity residual, no activation) ----
    k_gemm<<<gb, 256>>>(p_hB, W2, p_feat, N, 128);
    k_elr <<<N, 128>>>(p_feat, al2, ar2, p_el, p_er, N);
    k_edge<<<N, 128>>>(p_feat, p_el, p_er, p_rowptr, p_srcs, p_ews,
                       p_hB, b2, g2, be2, (float*)d_out, N, 0);
}